// round 8
// baseline (speedup 1.0000x reference)
#include <cuda_runtime.h>
#include <cstdint>

#define BT   4096
#define HDIM 2048
#define VDIM 32000
#define KC1  (HDIM / 8)            // 256 k8-chunks (gemm1)
#define KC2  (VDIM / 8)            // 4000 k8-chunks (gemm2)
#define SPLIT 5                    // gemm2 K-split
#define NZSL 500                   // z-partial slices: 250 n-tiles * 2 wn

// Output layout: [loss(1) | logits(BT*V) | lse(BT) | ntl(BT) | grad_x(BT*H)]
#define OUT_LOSS   0
#define OUT_LOGITS 1LL
#define OUT_LSE    (1LL + (long long)BT * VDIM)
#define OUT_NTL    (OUT_LSE + BT)
#define OUT_GRADX  (OUT_NTL + BT)

// GEMM geometry: CTA 384m x 128n, BK=32, 8 warps (4m x 2n), warp tile 96x64
#define BM 384
#define BN 128
#define BK 32
#define STG_AW 12288               // 24 m16-tiles * 4 kc * 128 words
#define STG_W  16384               // + 16 n8-tiles * 4 kc * 64 words
#define G_SMEM (3 * STG_W * 4)     // 196608 B, 3 stages

// ---- scratch ----
// A-perm: [m16][k8][lane][4] : j0=(g,tg) j1=(g+8,tg) j2=(g,tg+4) j3=(g+8,tg+4)
// B-perm: [n8][k8][lane][2]  : j0=(n=g,k=tg) j1=(n=g,k=tg+4)
__device__ uint32_t g_xt   [(size_t)(BT / 16) * KC1 * 128];
__device__ uint32_t g_wt   [(size_t)(VDIM / 8) * KC1 * 64];   // (n=v,k=h)
__device__ uint32_t g_wt2  [(size_t)(HDIM / 8) * KC2 * 64];   // (n=h,k=v)
__device__ uint32_t g_probs[(size_t)(BT / 16) * KC2 * 128];
__device__ float    g_gpart[(size_t)SPLIT * BT * HDIM];
__device__ float    g_zpart[(size_t)NZSL * BT];
__device__ float    g_scale[BT];

__device__ __forceinline__ uint32_t f2tf(float x) {
    uint32_t r;
    asm("cvt.rna.tf32.f32 %0, %1;" : "=r"(r) : "f"(x));
    return r;
}
__device__ __forceinline__ void mma8(float* d, const uint32_t* a, const uint32_t* b) {
    asm volatile(
        "mma.sync.aligned.m16n8k8.row.col.f32.tf32.tf32.f32 "
        "{%0,%1,%2,%3}, {%4,%5,%6,%7}, {%8,%9}, {%0,%1,%2,%3};\n"
        : "+f"(d[0]), "+f"(d[1]), "+f"(d[2]), "+f"(d[3])
        : "r"(a[0]), "r"(a[1]), "r"(a[2]), "r"(a[3]),
          "r"(b[0]), "r"(b[1]));
}
__device__ __forceinline__ void cpa16(uint32_t smem, const void* gmem) {
    asm volatile("cp.async.cg.shared.global [%0], [%1], 16;\n" :: "r"(smem), "l"(gmem));
}
__device__ __forceinline__ void cpa_commit() {
    asm volatile("cp.async.commit_group;\n" ::: "memory");
}
__device__ __forceinline__ void cpa_wait0() {
    asm volatile("cp.async.wait_group 0;\n" ::: "memory");
}
__device__ __forceinline__ void cpa_wait1() {
    asm volatile("cp.async.wait_group 1;\n" ::: "memory");
}

// ---------------------------------------------------------------------------
// Converters into fragment-major layouts
// ---------------------------------------------------------------------------
__global__ void convA_kernel(const float* __restrict__ x)
{
    const int lane = threadIdx.x & 31;
    const int g = lane >> 2, tg = lane & 3;
    const int warp = (blockIdx.x * blockDim.x + threadIdx.x) >> 5;
    const int nwarp = (gridDim.x * blockDim.x) >> 5;
    const int NF = (BT / 16) * KC1;
    for (int f = warp; f < NF; f += nwarp) {
        int m16 = f >> 8, kc = f & (KC1 - 1);
        const float* p = x + (size_t)(m16 * 16 + g) * HDIM + kc * 8 + tg;
        uint4 o = { f2tf(p[0]), f2tf(p[8 * HDIM]), f2tf(p[4]), f2tf(p[8 * HDIM + 4]) };
        *(uint4*)(g_xt + (size_t)f * 128 + lane * 4) = o;
    }
}
__global__ void convB1_kernel(const float* __restrict__ w)
{
    const int lane = threadIdx.x & 31;
    const int g = lane >> 2, tg = lane & 3;
    const int warp = (blockIdx.x * blockDim.x + threadIdx.x) >> 5;
    const int nwarp = (gridDim.x * blockDim.x) >> 5;
    const int NF = (VDIM / 8) * KC1;
    for (int f = warp; f < NF; f += nwarp) {
        int v8 = f >> 8, kc = f & (KC1 - 1);
        const float* p = w + (size_t)(v8 * 8 + g) * HDIM + kc * 8 + tg;
        uint2 o = { f2tf(p[0]), f2tf(p[4]) };
        *(uint2*)(g_wt + (size_t)f * 64 + lane * 2) = o;
    }
}
__global__ void convB2_kernel(const float* __restrict__ w)
{
    const int lane = threadIdx.x & 31;
    const int g = lane >> 2, tg = lane & 3;
    const int warp = (blockIdx.x * blockDim.x + threadIdx.x) >> 5;
    const int nwarp = (gridDim.x * blockDim.x) >> 5;
    const int NF = (HDIM / 8) * KC2;
    for (int f = warp; f < NF; f += nwarp) {
        int h8 = f / KC2, vc = f - h8 * KC2;
        const float* p = w + (size_t)(vc * 8 + tg) * HDIM + h8 * 8 + g;
        uint2 o = { f2tf(p[0]), f2tf(p[4 * HDIM]) };
        *(uint2*)(g_wt2 + (size_t)f * 64 + lane * 2) = o;
    }
}

// ---------------------------------------------------------------------------
// shared mainloop pieces (384x128 CTA, warp 96x64, BK=32, 3-stage, 1 sync/iter)
// ---------------------------------------------------------------------------
#define GEMM_DECLS                                            \
    const int tid  = threadIdx.x;                             \
    const int lane = tid & 31;                                \
    const int wid  = tid >> 5;                                \
    const int g    = lane >> 2;                               \
    const int tg   = lane & 3;                                \
    const int wm   = wid & 3;                                 \
    const int wn   = wid >> 2;                                \
    float acc[6][8][4];                                       \
    _Pragma("unroll")                                         \
    for (int i = 0; i < 6; i++)                               \
        _Pragma("unroll")                                     \
        for (int j = 0; j < 8; j++)                           \
            _Pragma("unroll")                                 \
            for (int q = 0; q < 4; q++) acc[i][j][q] = 0.f;

#define GEMM_ISSUE(AG, BG, KCD)                                               \
    auto issue = [&](int kt) {                                                \
        const uint32_t sb = smb + (uint32_t)(kt % 3) * (STG_W * 4);           \
        const int kc0 = kt * 4;                                              \
        _Pragma("unroll")                                                     \
        for (int i = 0; i < 12; i++) {            /* A: 3072 chunks */        \
            int q = tid + i * 256;                                            \
            int ai = q >> 7, rem = q & 127;                                   \
            int kcl = rem >> 5, c = rem & 31;                                 \
            cpa16(sb + (ai * 512 + kcl * 128 + c * 4) * 4,                    \
                  AG + ((size_t)(m0 / 16 + ai) * KCD + kc0 + kcl) * 128 + c * 4); \
        }                                                                     \
        _Pragma("unroll")                                                     \
        for (int i = 0; i < 4; i++) {             /* B: 1024 chunks */        \
            int q = tid + i * 256;                                            \
            int bj = q >> 6, rem = q & 63;                                    \
            int kcl = rem >> 4, c = rem & 15;                                 \
            cpa16(sb + (STG_AW + bj * 256 + kcl * 64 + c * 4) * 4,            \
                  BG + ((size_t)(n0 / 8 + bj) * KCD + kc0 + kcl) * 64 + c * 4); \
        }                                                                     \
        cpa_commit();                                                         \
    };

#define GEMM_COMPUTE(kt)                                                      \
    {                                                                         \
        const uint32_t* Aw = sm + (kt % 3) * STG_W;                           \
        const uint32_t* Bw = Aw + STG_AW;                                     \
        _Pragma("unroll")                                                     \
        for (int kc = 0; kc < 4; kc++) {                                      \
            uint4 av[6];                                                      \
            _Pragma("unroll")                                                 \
            for (int mt = 0; mt < 6; mt++)                                    \
                av[mt] = *(const uint4*)(Aw + (wm * 6 + mt) * 512 + kc * 128 + lane * 4); \
            _Pragma("unroll")                                                 \
            for (int nt = 0; nt < 8; nt++) {                                  \
                uint2 bv = *(const uint2*)(Bw + (wn * 8 + nt) * 256 + kc * 64 + lane * 2); \
                _Pragma("unroll")                                             \
                for (int mt = 0; mt < 6; mt++)                                \
                    mma8(acc[mt][nt], (const uint32_t*)&av[mt], (const uint32_t*)&bv); \
            }                                                                 \
        }                                                                     \
    }

// ---------------------------------------------------------------------------
// Phase 1: logits = x @ w^T. Epilogue: z partials (from acc), logits, probs.
// Last m-CTA overlaps (m0 clamped) — duplicate writes are identical values.
// ---------------------------------------------------------------------------
__global__ __launch_bounds__(256, 1) void gemm1_kernel(float* __restrict__ out)
{
    extern __shared__ uint32_t sm[];
    const uint32_t smb = (uint32_t)__cvta_generic_to_shared(sm);
    GEMM_DECLS
    const int m0 = min((int)blockIdx.x * BM, BT - BM);
    const int n0 = blockIdx.y * BN;
    GEMM_ISSUE(g_xt, g_wt, KC1)

    issue(0); issue(1);
    const int NK = HDIM / BK;   // 64
    for (int kt = 0; kt < NK; kt++) {
        if (kt + 1 < NK) cpa_wait1(); else cpa_wait0();
        __syncthreads();
        if (kt + 2 < NK) issue(kt + 2);
        GEMM_COMPUTE(kt)
    }

    // ---- z partials straight from fragments ----
    {
        float* zp = g_zpart + ((size_t)(blockIdx.y * 2 + wn)) * BT + m0;
        #pragma unroll
        for (int mt = 0; mt < 6; mt++) {
            float s0 = 0.f, s1 = 0.f;
            #pragma unroll
            for (int nt = 0; nt < 8; nt++) {
                s0 += __expf(acc[mt][nt][0]) + __expf(acc[mt][nt][1]);
                s1 += __expf(acc[mt][nt][2]) + __expf(acc[mt][nt][3]);
            }
            s0 += __shfl_xor_sync(0xFFFFFFFFu, s0, 1);
            s0 += __shfl_xor_sync(0xFFFFFFFFu, s0, 2);
            s1 += __shfl_xor_sync(0xFFFFFFFFu, s1, 1);
            s1 += __shfl_xor_sync(0xFFFFFFFFu, s1, 2);
            if (tg == 0) {
                zp[wm * 96 + mt * 16 + g]     = s0;
                zp[wm * 96 + mt * 16 + 8 + g] = s1;
            }
        }
    }

    // ---- logits + probs in two 192-row halves ----
    float* sf = (float*)sm;                        // [192][132] = 101376 B
    float* outL = out + OUT_LOGITS;
    const int col = tid & 127;
    const int rh  = tid >> 7;
    #pragma unroll
    for (int p = 0; p < 2; p++) {
        __syncthreads();
        if ((wm >> 1) == p) {
            #pragma unroll
            for (int mt = 0; mt < 6; mt++) {
                #pragma unroll
                for (int nt = 0; nt < 8; nt++) {
                    int r = (wm & 1) * 96 + mt * 16 + g;
                    int c = wn * 64 + nt * 8 + tg * 2;
                    sf[r * 132 + c]           = acc[mt][nt][0];
                    sf[r * 132 + c + 1]       = acc[mt][nt][1];
                    sf[(r + 8) * 132 + c]     = acc[mt][nt][2];
                    sf[(r + 8) * 132 + c + 1] = acc[mt][nt][3];
                }
            }
        }
        __syncthreads();
        // logits (coalesced)
        #pragma unroll 8
        for (int i = 0; i < 96; i++) {
            int r = i * 2 + rh;
            outL[(size_t)(m0 + p * 192 + r) * VDIM + n0 + col] = sf[r * 132 + col];
        }
        // probs in A-perm layout: 192 fragment units, 24 per warp
        #pragma unroll 4
        for (int u = 0; u < 24; u++) {
            int unit = wid * 24 + u;
            int t16 = unit >> 4, vc = unit & 15;
            int rb = t16 * 16;
            float e0 = __expf(sf[(rb + g) * 132 + vc * 8 + tg]);
            float e1 = __expf(sf[(rb + 8 + g) * 132 + vc * 8 + tg]);
            float e2 = __expf(sf[(rb + g) * 132 + vc * 8 + tg + 4]);
            float e3 = __expf(sf[(rb + 8 + g) * 132 + vc * 8 + tg + 4]);
            uint4 o = { f2tf(e0), f2tf(e1), f2tf(e2), f2tf(e3) };
            *(uint4*)(g_probs + ((size_t)(m0 / 16 + p * 12 + t16) * KC2
                                 + n0 / 8 + vc) * 128 + lane * 4) = o;
        }
    }
}

// ---------------------------------------------------------------------------
// Phase 2: zred — Z, lse, 1/Z, ntl. Target dtype runtime-detected
// (JAX x64-off downcasts int64 -> int32; odd words all-zero => int64).
// ---------------------------------------------------------------------------
__global__ void zred_kernel(const void* __restrict__ target,
                            float* __restrict__ out)
{
    __shared__ int oddor;
    const int tid = threadIdx.x;
    const int lane = tid & 31;
    const int wid = tid >> 5;
    const int row = blockIdx.x * 8 + wid;

    if (tid == 0) oddor = 0;
    __syncthreads();
    {
        const int* t32 = (const int*)target;
        int f = 0;
        for (int i = tid; i < BT / 2; i += 256) f |= t32[2 * i + 1];
        if (f) atomicOr(&oddor, 1);
    }
    __syncthreads();

    float s = 0.f;
    for (int t = lane; t < NZSL; t += 32)
        s += g_zpart[(size_t)t * BT + row];
    #pragma unroll
    for (int o = 16; o > 0; o >>= 1)
        s += __shfl_xor_sync(0xFFFFFFFFu, s, o);

    if (lane == 0) {
        out[OUT_LSE + row] = logf(s);
        g_scale[row] = 1.0f / s;
        long long t;
        if (oddor) t = (long long)((const int*)target)[row];
        else       t = ((const long long*)target)[row];
        if (t < 0) t = 0;
        if (t >= VDIM) t = VDIM - 1;
        out[OUT_NTL + row] = -out[OUT_LOGITS + (size_t)row * VDIM + t];
    }
}

__global__ void loss_kernel(float* __restrict__ out)
{
    __shared__ float red[256];
    const int tid = threadIdx.x;
    float s = 0.f;
    for (int i = tid; i < BT; i += 256)
        s += out[OUT_LSE + i] + out[OUT_NTL + i];
    red[tid] = s;
    __syncthreads();
    for (int st = 128; st > 0; st >>= 1) {
        if (tid < st) red[tid] += red[tid + st];
        __syncthreads();
    }
    if (tid == 0) out[OUT_LOSS] = red[0] / (float)BT;
}

// ---------------------------------------------------------------------------
// Phase 3: grad partials = E @ w (K-split x5), direct fragment stores
// ---------------------------------------------------------------------------
__global__ __launch_bounds__(256, 1) void gemm2_kernel()
{
    extern __shared__ uint32_t sm[];
    const uint32_t smb = (uint32_t)__cvta_generic_to_shared(sm);
    GEMM_DECLS
    const int m0 = min((int)blockIdx.x * BM, BT - BM);
    const int n0 = blockIdx.y * BN;
    const int s  = blockIdx.z;
    GEMM_ISSUE(g_probs, g_wt2, KC2)

    const int kbase = s * (VDIM / BK / SPLIT);    // 200 iters per split
    const int kend  = kbase + (VDIM / BK / SPLIT);
    issue(kbase); issue(kbase + 1);
    for (int kt = kbase; kt < kend; kt++) {
        if (kt + 1 < kend) cpa_wait1(); else cpa_wait0();
        __syncthreads();
        if (kt + 2 < kend) issue(kt + 2);
        GEMM_COMPUTE(kt)
    }

    float* gp = g_gpart + (size_t)s * BT * HDIM;
    #pragma unroll
    for (int mt = 0; mt < 6; mt++) {
        #pragma unroll
        for (int nt = 0; nt < 8; nt++) {
            int r = m0 + wm * 96 + mt * 16 + g;
            int c = n0 + wn * 64 + nt * 8 + tg * 2;
            *(float2*)(gp + (size_t)r * HDIM + c) =
                make_float2(acc[mt][nt][0], acc[mt][nt][1]);
            *(float2*)(gp + (size_t)(r + 8) * HDIM + c) =
                make_float2(acc[mt][nt][2], acc[mt][nt][3]);
        }
    }
}

// ---------------------------------------------------------------------------
// Phase 4: grad_x = (sum_s partial) * 1/Z
// ---------------------------------------------------------------------------
__global__ void gradred_kernel(float* __restrict__ out)
{
    const int row = blockIdx.x;
    const float sc = g_scale[row];
    float* o = out + OUT_GRADX + (size_t)row * HDIM;
    const float* p = g_gpart + (size_t)row * HDIM;
    for (int c = threadIdx.x; c < HDIM; c += 256) {
        float v = p[c];
        #pragma unroll
        for (int s = 1; s < SPLIT; s++)
            v += p[(size_t)s * BT * HDIM + c];
        o[c] = v * sc;
    }
}

// ---------------------------------------------------------------------------
extern "C" void kernel_launch(void* const* d_in, const int* in_sizes, int n_in,
                              void* d_out, int out_size)
{
    const float* x   = (const float*)d_in[0];
    const float* w   = (const float*)d_in[1];
    const void*  tgt = d_in[2];
    float*       out = (float*)d_out;

    cudaFuncSetAttribute(gemm1_kernel,
        cudaFuncAttributeMaxDynamicSharedMemorySize, G_SMEM);
    cudaFuncSetAttribute(gemm2_kernel,
        cudaFuncAttributeMaxDynamicSharedMemorySize, G_SMEM);

    convA_kernel <<<512,  128>>>(x);
    convB1_kernel<<<4096, 128>>>(w);
    convB2_kernel<<<4096, 128>>>(w);

    dim3 g1((BT + BM - 1) / BM, VDIM / BN);     // (11, 250), m-fastest
    gemm1_kernel<<<g1, 256, G_SMEM>>>(out);

    zred_kernel<<<BT / 8, 256>>>(tgt, out);
    loss_kernel<<<1, 256>>>(out);

    dim3 g2((BT + BM - 1) / BM, HDIM / BN, SPLIT);  // (11, 16, 5)
    gemm2_kernel<<<g2, 256, G_SMEM>>>();
    gradred_kernel<<<BT, 256>>>(out);
}

// round 9
// speedup vs baseline: 1.0398x; 1.0398x over previous
#include <cuda_runtime.h>
#include <cstdint>

#define BT   4096
#define HDIM 2048
#define VDIM 32000
#define KC1  (HDIM / 8)            // 256 k8-chunks (gemm1)
#define KC2  (VDIM / 8)            // 4000 k8-chunks (gemm2)
#define SPLIT 4                    // gemm2 K-split
#define NZSL 500                   // z slices: 125 n-tiles * 4 wn groups

// Output layout: [loss(1) | logits(BT*V) | lse(BT) | ntl(BT) | grad_x(BT*H)]
#define OUT_LOSS   0
#define OUT_LOGITS 1LL
#define OUT_LSE    (1LL + (long long)BT * VDIM)
#define OUT_NTL    (OUT_LSE + BT)
#define OUT_GRADX  (OUT_NTL + BT)

// GEMM geometry: CTA 128m x 256n, BK=32, 512 thr, 16 warps (4m x 4n), warp 32x64
#define BM 128
#define BN 256
#define BK 32
#define STG_AW 4096                // 8 m16-tiles * 4 kc * 128 words
#define STG_W  12288               // + 32 n8-tiles * 4 kc * 64 words
#define G_SMEM (3 * STG_W * 4)     // 147456 B, 3 stages

// ---- scratch ----
// A-perm: [m16][k8][lane][4] : j0=(g,tg) j1=(g+8,tg) j2=(g,tg+4) j3=(g+8,tg+4)
// B-perm: [n8][k8][lane][2]  : j0=(n=g,k=tg) j1=(n=g,k=tg+4)
__device__ uint32_t g_xt   [(size_t)(BT / 16) * KC1 * 128];
__device__ uint32_t g_wt   [(size_t)(VDIM / 8) * KC1 * 64];   // (n=v,k=h)
__device__ uint32_t g_wt2  [(size_t)(HDIM / 8) * KC2 * 64];   // (n=h,k=v)
__device__ uint32_t g_probs[(size_t)(BT / 16) * KC2 * 128];
__device__ float    g_gpart[(size_t)SPLIT * BT * HDIM];
__device__ float    g_zpart[(size_t)NZSL * BT];
__device__ float    g_scale[BT];

__device__ __forceinline__ uint32_t f2tf(float x) {
    uint32_t r;
    asm("cvt.rna.tf32.f32 %0, %1;" : "=r"(r) : "f"(x));
    return r;
}
__device__ __forceinline__ void mma8(float* d, const uint32_t* a, const uint32_t* b) {
    asm volatile(
        "mma.sync.aligned.m16n8k8.row.col.f32.tf32.tf32.f32 "
        "{%0,%1,%2,%3}, {%4,%5,%6,%7}, {%8,%9}, {%0,%1,%2,%3};\n"
        : "+f"(d[0]), "+f"(d[1]), "+f"(d[2]), "+f"(d[3])
        : "r"(a[0]), "r"(a[1]), "r"(a[2]), "r"(a[3]),
          "r"(b[0]), "r"(b[1]));
}
__device__ __forceinline__ void cpa16(uint32_t smem, const void* gmem) {
    asm volatile("cp.async.cg.shared.global [%0], [%1], 16;\n" :: "r"(smem), "l"(gmem));
}
__device__ __forceinline__ void cpa_commit() {
    asm volatile("cp.async.commit_group;\n" ::: "memory");
}
__device__ __forceinline__ void cpa_wait0() {
    asm volatile("cp.async.wait_group 0;\n" ::: "memory");
}
__device__ __forceinline__ void cpa_wait1() {
    asm volatile("cp.async.wait_group 1;\n" ::: "memory");
}

// ---------------------------------------------------------------------------
// Converters into fragment-major layouts
// ---------------------------------------------------------------------------
__global__ void convA_kernel(const float* __restrict__ x)
{
    const int lane = threadIdx.x & 31;
    const int g = lane >> 2, tg = lane & 3;
    const int warp = (blockIdx.x * blockDim.x + threadIdx.x) >> 5;
    const int nwarp = (gridDim.x * blockDim.x) >> 5;
    const int NF = (BT / 16) * KC1;
    for (int f = warp; f < NF; f += nwarp) {
        int m16 = f >> 8, kc = f & (KC1 - 1);
        const float* p = x + (size_t)(m16 * 16 + g) * HDIM + kc * 8 + tg;
        uint4 o = { f2tf(p[0]), f2tf(p[8 * HDIM]), f2tf(p[4]), f2tf(p[8 * HDIM + 4]) };
        *(uint4*)(g_xt + (size_t)f * 128 + lane * 4) = o;
    }
}
__global__ void convB1_kernel(const float* __restrict__ w)
{
    const int lane = threadIdx.x & 31;
    const int g = lane >> 2, tg = lane & 3;
    const int warp = (blockIdx.x * blockDim.x + threadIdx.x) >> 5;
    const int nwarp = (gridDim.x * blockDim.x) >> 5;
    const int NF = (VDIM / 8) * KC1;
    for (int f = warp; f < NF; f += nwarp) {
        int v8 = f >> 8, kc = f & (KC1 - 1);
        const float* p = w + (size_t)(v8 * 8 + g) * HDIM + kc * 8 + tg;
        uint2 o = { f2tf(p[0]), f2tf(p[4]) };
        *(uint2*)(g_wt + (size_t)f * 64 + lane * 2) = o;
    }
}
__global__ void convB2_kernel(const float* __restrict__ w)
{
    const int lane = threadIdx.x & 31;
    const int g = lane >> 2, tg = lane & 3;
    const int warp = (blockIdx.x * blockDim.x + threadIdx.x) >> 5;
    const int nwarp = (gridDim.x * blockDim.x) >> 5;
    const int NF = (HDIM / 8) * KC2;
    for (int f = warp; f < NF; f += nwarp) {
        int h8 = f / KC2, vc = f - h8 * KC2;
        const float* p = w + (size_t)(vc * 8 + tg) * HDIM + h8 * 8 + g;
        uint2 o = { f2tf(p[0]), f2tf(p[4 * HDIM]) };
        *(uint2*)(g_wt2 + (size_t)f * 64 + lane * 2) = o;
    }
}

// ---------------------------------------------------------------------------
// mainloop pieces: 128x256 CTA, warp 32x64, BK=32, 3-stage, 1 sync/iter
// ---------------------------------------------------------------------------
#define GEMM_DECLS                                            \
    const int tid  = threadIdx.x;                             \
    const int lane = tid & 31;                                \
    const int wid  = tid >> 5;                                \
    const int g    = lane >> 2;                               \
    const int tg   = lane & 3;                                \
    const int wm   = wid & 3;                                 \
    const int wn   = wid >> 2;                                \
    float acc[2][8][4];                                       \
    _Pragma("unroll")                                         \
    for (int i = 0; i < 2; i++)                               \
        _Pragma("unroll")                                     \
        for (int j = 0; j < 8; j++)                           \
            _Pragma("unroll")                                 \
            for (int q = 0; q < 4; q++) acc[i][j][q] = 0.f;

#define GEMM_ISSUE(AG, BG, KCD)                                               \
    auto issue = [&](int kt) {                                                \
        const uint32_t sb = smb + (uint32_t)(kt % 3) * (STG_W * 4);           \
        const int kc0 = kt * 4;                                              \
        _Pragma("unroll")                                                     \
        for (int i = 0; i < 2; i++) {             /* A: 1024 chunks */        \
            int q = tid + i * 512;                                            \
            int ai = q >> 7, rem = q & 127;                                   \
            int kcl = rem >> 5, c = rem & 31;                                 \
            cpa16(sb + (ai * 512 + kcl * 128 + c * 4) * 4,                    \
                  AG + ((size_t)(m0 / 16 + ai) * KCD + kc0 + kcl) * 128 + c * 4); \
        }                                                                     \
        _Pragma("unroll")                                                     \
        for (int i = 0; i < 4; i++) {             /* B: 2048 chunks */        \
            int q = tid + i * 512;                                            \
            int bj = q >> 6, rem = q & 63;                                    \
            int kcl = rem >> 4, c = rem & 15;                                 \
            cpa16(sb + (STG_AW + bj * 256 + kcl * 64 + c * 4) * 4,            \
                  BG + ((size_t)(n0 / 8 + bj) * KCD + kc0 + kcl) * 64 + c * 4); \
        }                                                                     \
        cpa_commit();                                                         \
    };

#define GEMM_COMPUTE(kt)                                                      \
    {                                                                         \
        const uint32_t* Aw = sm + (kt % 3) * STG_W;                           \
        const uint32_t* Bw = Aw + STG_AW;                                     \
        _Pragma("unroll")                                                     \
        for (int kc = 0; kc < 4; kc++) {                                      \
            uint4 av[2];                                                      \
            _Pragma("unroll")                                                 \
            for (int mt = 0; mt < 2; mt++)                                    \
                av[mt] = *(const uint4*)(Aw + (wm * 2 + mt) * 512 + kc * 128 + lane * 4); \
            _Pragma("unroll")                                                 \
            for (int nt = 0; nt < 8; nt++) {                                  \
                uint2 bv = *(const uint2*)(Bw + (wn * 8 + nt) * 256 + kc * 64 + lane * 2); \
                _Pragma("unroll")                                             \
                for (int mt = 0; mt < 2; mt++)                                \
                    mma8(acc[mt][nt], (const uint32_t*)&av[mt], (const uint32_t*)&bv); \
            }                                                                 \
        }                                                                     \
    }

// ---------------------------------------------------------------------------
// Phase 1: logits = x @ w^T. Epilogue: z partials (from acc), logits, probs.
// ---------------------------------------------------------------------------
__global__ __launch_bounds__(512, 1) void gemm1_kernel(float* __restrict__ out)
{
    extern __shared__ uint32_t sm[];
    const uint32_t smb = (uint32_t)__cvta_generic_to_shared(sm);
    GEMM_DECLS
    const int m0 = blockIdx.x * BM;
    const int n0 = blockIdx.y * BN;
    GEMM_ISSUE(g_xt, g_wt, KC1)

    issue(0); issue(1);
    const int NK = HDIM / BK;   // 64
    for (int kt = 0; kt < NK; kt++) {
        if (kt + 1 < NK) cpa_wait1(); else cpa_wait0();
        __syncthreads();
        if (kt + 2 < NK) issue(kt + 2);
        GEMM_COMPUTE(kt)
    }

    // ---- z partials straight from fragments ----
    {
        float* zp = g_zpart + ((size_t)(blockIdx.y * 4 + wn)) * BT + m0;
        #pragma unroll
        for (int mt = 0; mt < 2; mt++) {
            float s0 = 0.f, s1 = 0.f;
            #pragma unroll
            for (int nt = 0; nt < 8; nt++) {
                s0 += __expf(acc[mt][nt][0]) + __expf(acc[mt][nt][1]);
                s1 += __expf(acc[mt][nt][2]) + __expf(acc[mt][nt][3]);
            }
            s0 += __shfl_xor_sync(0xFFFFFFFFu, s0, 1);
            s0 += __shfl_xor_sync(0xFFFFFFFFu, s0, 2);
            s1 += __shfl_xor_sync(0xFFFFFFFFu, s1, 1);
            s1 += __shfl_xor_sync(0xFFFFFFFFu, s1, 2);
            if (tg == 0) {
                zp[wm * 32 + mt * 16 + g]     = s0;
                zp[wm * 32 + mt * 16 + 8 + g] = s1;
            }
        }
    }

    // ---- stage full 128x256 tile, then logits + probs ----
    __syncthreads();
    float* sf = (float*)sm;                        // [128][260] = 133120 B
    #pragma unroll
    for (int mt = 0; mt < 2; mt++) {
        #pragma unroll
        for (int nt = 0; nt < 8; nt++) {
            int r = wm * 32 + mt * 16 + g;
            int c = wn * 64 + nt * 8 + tg * 2;
            sf[r * 260 + c]           = acc[mt][nt][0];
            sf[r * 260 + c + 1]       = acc[mt][nt][1];
            sf[(r + 8) * 260 + c]     = acc[mt][nt][2];
            sf[(r + 8) * 260 + c + 1] = acc[mt][nt][3];
        }
    }
    __syncthreads();

    float* outL = out + OUT_LOGITS;
    const int col = tid & 255;
    const int rh  = tid >> 8;
    #pragma unroll 8
    for (int i = 0; i < 64; i++) {
        int r = i * 2 + rh;
        outL[(size_t)(m0 + r) * VDIM + n0 + col] = sf[r * 260 + col];
    }
    // probs in A-perm layout: 8 m16-tiles * 32 vc = 256 units, 16 per warp
    #pragma unroll 4
    for (int u = 0; u < 16; u++) {
        int unit = wid * 16 + u;
        int t16 = unit >> 5, vc = unit & 31;
        int rb = t16 * 16;
        float e0 = __expf(sf[(rb + g) * 260 + vc * 8 + tg]);
        float e1 = __expf(sf[(rb + 8 + g) * 260 + vc * 8 + tg]);
        float e2 = __expf(sf[(rb + g) * 260 + vc * 8 + tg + 4]);
        float e3 = __expf(sf[(rb + 8 + g) * 260 + vc * 8 + tg + 4]);
        uint4 o = { f2tf(e0), f2tf(e1), f2tf(e2), f2tf(e3) };
        *(uint4*)(g_probs + ((size_t)(m0 / 16 + t16) * KC2 + n0 / 8 + vc) * 128
                  + lane * 4) = o;
    }
}

// ---------------------------------------------------------------------------
// Phase 2: zred — Z, lse, 1/Z, ntl. Target dtype runtime-detected
// (JAX x64-off downcasts int64 -> int32; odd words all-zero => int64).
// ---------------------------------------------------------------------------
__global__ void zred_kernel(const void* __restrict__ target,
                            float* __restrict__ out)
{
    __shared__ int oddor;
    const int tid = threadIdx.x;
    const int lane = tid & 31;
    const int wid = tid >> 5;
    const int row = blockIdx.x * 8 + wid;

    if (tid == 0) oddor = 0;
    __syncthreads();
    {
        const int* t32 = (const int*)target;
        int f = 0;
        for (int i = tid; i < BT / 2; i += 256) f |= t32[2 * i + 1];
        if (f) atomicOr(&oddor, 1);
    }
    __syncthreads();

    float s = 0.f;
    for (int t = lane; t < NZSL; t += 32)
        s += g_zpart[(size_t)t * BT + row];
    #pragma unroll
    for (int o = 16; o > 0; o >>= 1)
        s += __shfl_xor_sync(0xFFFFFFFFu, s, o);

    if (lane == 0) {
        out[OUT_LSE + row] = logf(s);
        g_scale[row] = 1.0f / s;
        long long t;
        if (oddor) t = (long long)((const int*)target)[row];
        else       t = ((const long long*)target)[row];
        if (t < 0) t = 0;
        if (t >= VDIM) t = VDIM - 1;
        out[OUT_NTL + row] = -out[OUT_LOGITS + (size_t)row * VDIM + t];
    }
}

__global__ void loss_kernel(float* __restrict__ out)
{
    __shared__ float red[256];
    const int tid = threadIdx.x;
    float s = 0.f;
    for (int i = tid; i < BT; i += 256)
        s += out[OUT_LSE + i] + out[OUT_NTL + i];
    red[tid] = s;
    __syncthreads();
    for (int st = 128; st > 0; st >>= 1) {
        if (tid < st) red[tid] += red[tid + st];
        __syncthreads();
    }
    if (tid == 0) out[OUT_LOSS] = red[0] / (float)BT;
}

// ---------------------------------------------------------------------------
// Phase 3: grad partials = E @ w (K-split x4), direct fragment stores
// ---------------------------------------------------------------------------
__global__ __launch_bounds__(512, 1) void gemm2_kernel()
{
    extern __shared__ uint32_t sm[];
    const uint32_t smb = (uint32_t)__cvta_generic_to_shared(sm);
    GEMM_DECLS
    const int m0 = blockIdx.x * BM;
    const int n0 = blockIdx.y * BN;
    const int s  = blockIdx.z;
    GEMM_ISSUE(g_probs, g_wt2, KC2)

    const int kbase = s * (VDIM / BK / SPLIT);    // 250 iters per split
    const int kend  = kbase + (VDIM / BK / SPLIT);
    issue(kbase); issue(kbase + 1);
    for (int kt = kbase; kt < kend; kt++) {
        if (kt + 1 < kend) cpa_wait1(); else cpa_wait0();
        __syncthreads();
        if (kt + 2 < kend) issue(kt + 2);
        GEMM_COMPUTE(kt)
    }

    float* gp = g_gpart + (size_t)s * BT * HDIM;
    #pragma unroll
    for (int mt = 0; mt < 2; mt++) {
        #pragma unroll
        for (int nt = 0; nt < 8; nt++) {
            int r = m0 + wm * 32 + mt * 16 + g;
            int c = n0 + wn * 64 + nt * 8 + tg * 2;
            *(float2*)(gp + (size_t)r * HDIM + c) =
                make_float2(acc[mt][nt][0], acc[mt][nt][1]);
            *(float2*)(gp + (size_t)(r + 8) * HDIM + c) =
                make_float2(acc[mt][nt][2], acc[mt][nt][3]);
        }
    }
}

// ---------------------------------------------------------------------------
// Phase 4: grad_x = (sum_s partial) * 1/Z
// ---------------------------------------------------------------------------
__global__ void gradred_kernel(float* __restrict__ out)
{
    const int row = blockIdx.x;
    const float sc = g_scale[row];
    float* o = out + OUT_GRADX + (size_t)row * HDIM;
    const float* p = g_gpart + (size_t)row * HDIM;
    for (int c = threadIdx.x; c < HDIM; c += 256) {
        float v = p[c];
        #pragma unroll
        for (int s = 1; s < SPLIT; s++)
            v += p[(size_t)s * BT * HDIM + c];
        o[c] = v * sc;
    }
}

// ---------------------------------------------------------------------------
extern "C" void kernel_launch(void* const* d_in, const int* in_sizes, int n_in,
                              void* d_out, int out_size)
{
    const float* x   = (const float*)d_in[0];
    const float* w   = (const float*)d_in[1];
    const void*  tgt = d_in[2];
    float*       out = (float*)d_out;

    cudaFuncSetAttribute(gemm1_kernel,
        cudaFuncAttributeMaxDynamicSharedMemorySize, G_SMEM);
    cudaFuncSetAttribute(gemm2_kernel,
        cudaFuncAttributeMaxDynamicSharedMemorySize, G_SMEM);

    convA_kernel <<<512,  128>>>(x);
    convB1_kernel<<<4096, 128>>>(w);
    convB2_kernel<<<4096, 128>>>(w);

    dim3 g1(BT / BM, VDIM / BN);        // (32, 125), m-fastest
    gemm1_kernel<<<g1, 512, G_SMEM>>>(out);

    zred_kernel<<<BT / 8, 256>>>(tgt, out);
    loss_kernel<<<1, 256>>>(out);

    dim3 g2(BT / BM, HDIM / BN, SPLIT); // (32, 8, 4) = 1024 CTAs
    gemm2_kernel<<<g2, 512, G_SMEM>>>();
    gradred_kernel<<<BT, 256>>>(out);
}

// round 10
// speedup vs baseline: 2.1734x; 2.0901x over previous
#include <cuda_runtime.h>
#include <cuda_fp16.h>
#include <cstdint>

#define BT   4096
#define HDIM 2048
#define VDIM 32000
#define KC1H (HDIM / 16)           // 128 k16-chunks (gemm1)
#define KC2H (VDIM / 16)           // 2000 k16-chunks (gemm2)
#define SPLIT 4
#define NZSL 500                   // 250 n-tiles * 2 wn

// Output layout: [loss(1) | logits(BT*V) | lse(BT) | ntl(BT) | grad_x(BT*H)]
#define OUT_LOSS   0
#define OUT_LOGITS 1LL
#define OUT_LSE    (1LL + (long long)BT * VDIM)
#define OUT_NTL    (OUT_LSE + BT)
#define OUT_GRADX  (OUT_NTL + BT)

// Geometry: CTA 128x128, BK=32 (2 k16), 128 thr, 4 warps (2m x 2n), warp 64x64
#define BM 128
#define BN 128
#define STG_AW 2048                // 8 m16 * 2 kc * 128 words
#define STG_W  4096                // + 16 n8 * 2 kc * 64 words
#define G1_SMEM 67584              // max(3 stages = 49152, sf 128*132*4)
#define G2_SMEM 49152

// ---- scratch (fp16 fragment-major) ----
// A unit [m16][k16]: lane-> uint4 {(g,2tg|+1),(g+8,..),(g,2tg+8|+9),(g+8,..)}
// B unit [n8][k16]:  lane-> uint2 {(k=2tg|+1,n=g),(k=2tg+8|+9,n=g)}
__device__ uint32_t g_xt   [(size_t)(BT / 16) * KC1H * 128];
__device__ uint32_t g_wt   [(size_t)(VDIM / 8) * KC1H * 64];   // (n=v,k=h)
__device__ uint32_t g_wt2  [(size_t)(HDIM / 8) * KC2H * 64];   // (n=h,k=v)
__device__ uint32_t g_probs[(size_t)(BT / 16) * KC2H * 128];
__device__ float    g_gpart[(size_t)SPLIT * BT * HDIM];
__device__ float    g_zpart[(size_t)NZSL * BT];
__device__ float    g_scale[BT];

__device__ __forceinline__ uint32_t packh2(float lo, float hi) {
    __half2 h = __floats2half2_rn(lo, hi);
    return *(uint32_t*)&h;
}
__device__ __forceinline__ void mma16(float* d, const uint32_t* a, const uint32_t* b) {
    asm volatile(
        "mma.sync.aligned.m16n8k16.row.col.f32.f16.f16.f32 "
        "{%0,%1,%2,%3}, {%4,%5,%6,%7}, {%8,%9}, {%0,%1,%2,%3};\n"
        : "+f"(d[0]), "+f"(d[1]), "+f"(d[2]), "+f"(d[3])
        : "r"(a[0]), "r"(a[1]), "r"(a[2]), "r"(a[3]),
          "r"(b[0]), "r"(b[1]));
}
__device__ __forceinline__ void cpa16(uint32_t smem, const void* gmem) {
    asm volatile("cp.async.cg.shared.global [%0], [%1], 16;\n" :: "r"(smem), "l"(gmem));
}
__device__ __forceinline__ void cpa_commit() {
    asm volatile("cp.async.commit_group;\n" ::: "memory");
}
__device__ __forceinline__ void cpa_wait0() {
    asm volatile("cp.async.wait_group 0;\n" ::: "memory");
}
__device__ __forceinline__ void cpa_wait1() {
    asm volatile("cp.async.wait_group 1;\n" ::: "memory");
}

// ---------------------------------------------------------------------------
// Converters into fp16 fragment-major layouts
// ---------------------------------------------------------------------------
__global__ void convA_kernel(const float* __restrict__ x)
{
    const int lane = threadIdx.x & 31;
    const int g = lane >> 2, tg = lane & 3;
    const int warp = (blockIdx.x * blockDim.x + threadIdx.x) >> 5;
    const int nwarp = (gridDim.x * blockDim.x) >> 5;
    const int NF = (BT / 16) * KC1H;                 // 32768
    for (int f = warp; f < NF; f += nwarp) {
        int m16 = f >> 7, kc = f & (KC1H - 1);
        const float* p = x + (size_t)(m16 * 16 + g) * HDIM + kc * 16;
        uint4 o;
        o.x = packh2(p[2 * tg],            p[2 * tg + 1]);
        o.y = packh2(p[8 * HDIM + 2 * tg], p[8 * HDIM + 2 * tg + 1]);
        o.z = packh2(p[2 * tg + 8],        p[2 * tg + 9]);
        o.w = packh2(p[8 * HDIM + 2 * tg + 8], p[8 * HDIM + 2 * tg + 9]);
        *(uint4*)(g_xt + (size_t)f * 128 + lane * 4) = o;
    }
}
__global__ void convB1_kernel(const float* __restrict__ w)
{
    const int lane = threadIdx.x & 31;
    const int g = lane >> 2, tg = lane & 3;
    const int warp = (blockIdx.x * blockDim.x + threadIdx.x) >> 5;
    const int nwarp = (gridDim.x * blockDim.x) >> 5;
    const int NF = (VDIM / 8) * KC1H;                // 512000
    for (int f = warp; f < NF; f += nwarp) {
        int v8 = f >> 7, kc = f & (KC1H - 1);
        const float* p = w + (size_t)(v8 * 8 + g) * HDIM + kc * 16;
        uint2 o;
        o.x = packh2(p[2 * tg],     p[2 * tg + 1]);
        o.y = packh2(p[2 * tg + 8], p[2 * tg + 9]);
        *(uint2*)(g_wt + (size_t)f * 64 + lane * 2) = o;
    }
}
__global__ void convB2_kernel(const float* __restrict__ w)
{
    const int lane = threadIdx.x & 31;
    const int g = lane >> 2, tg = lane & 3;
    const int warp = (blockIdx.x * blockDim.x + threadIdx.x) >> 5;
    const int nwarp = (gridDim.x * blockDim.x) >> 5;
    const int NF = (HDIM / 8) * KC2H;                // 512000
    for (int f = warp; f < NF; f += nwarp) {
        int h8 = f / KC2H, kc = f - h8 * KC2H;
        const float* p = w + (size_t)(kc * 16) * HDIM + h8 * 8 + g;
        uint2 o;
        o.x = packh2(p[(2 * tg) * HDIM],     p[(2 * tg + 1) * HDIM]);
        o.y = packh2(p[(2 * tg + 8) * HDIM], p[(2 * tg + 9) * HDIM]);
        *(uint2*)(g_wt2 + (size_t)f * 64 + lane * 2) = o;
    }
}

// ---------------------------------------------------------------------------
// mainloop pieces: 128x128 CTA, warp 64x64, BK=32 (2 k16), 3-stage, 1 sync/iter
// ---------------------------------------------------------------------------
#define GEMM_DECLS                                            \
    const int tid  = threadIdx.x;                             \
    const int lane = tid & 31;                                \
    const int wid  = tid >> 5;                                \
    const int g    = lane >> 2;                               \
    const int tg   = lane & 3;                                \
    const int wm   = wid & 1;                                 \
    const int wn   = wid >> 1;                                \
    float acc[4][8][4];                                       \
    _Pragma("unroll")                                         \
    for (int i = 0; i < 4; i++)                               \
        _Pragma("unroll")                                     \
        for (int j = 0; j < 8; j++)                           \
            _Pragma("unroll")                                 \
            for (int q = 0; q < 4; q++) acc[i][j][q] = 0.f;

#define GEMM_ISSUE(AG, BG, KCD)                                               \
    auto issue = [&](int kt) {                                                \
        const uint32_t sb = smb + (uint32_t)(kt % 3) * (STG_W * 4);           \
        const int kc0 = kt * 2;                                              \
        _Pragma("unroll")                                                     \
        for (int i = 0; i < 4; i++) {             /* A: 512 chunks */         \
            int q = tid + i * 128;                                            \
            int ai = q >> 6, rem = q & 63;                                    \
            int kcl = rem >> 5, c = rem & 31;                                 \
            cpa16(sb + (ai * 256 + kcl * 128 + c * 4) * 4,                    \
                  AG + ((size_t)(m0 / 16 + ai) * KCD + kc0 + kcl) * 128 + c * 4); \
        }                                                                     \
        _Pragma("unroll")                                                     \
        for (int i = 0; i < 4; i++) {             /* B: 512 chunks */         \
            int q = tid + i * 128;                                            \
            int bj = q >> 5, rem = q & 31;                                    \
            int kcl = rem >> 4, c = rem & 15;                                 \
            cpa16(sb + (STG_AW + bj * 128 + kcl * 64 + c * 4) * 4,            \
                  BG + ((size_t)(n0 / 8 + bj) * KCD + kc0 + kcl) * 64 + c * 4); \
        }                                                                     \
        cpa_commit();                                                         \
    };

#define GEMM_COMPUTE(kt)                                                      \
    {                                                                         \
        const uint32_t* Aw = sm + (kt % 3) * STG_W;                           \
        const uint32_t* Bw = Aw + STG_AW;                                     \
        _Pragma("unroll")                                                     \
        for (int kc = 0; kc < 2; kc++) {                                      \
            uint4 av[4];                                                      \
            _Pragma("unroll")                                                 \
            for (int mt = 0; mt < 4; mt++)                                    \
                av[mt] = *(const uint4*)(Aw + (wm * 4 + mt) * 256 + kc * 128 + lane * 4); \
            _Pragma("unroll")                                                 \
            for (int nt = 0; nt < 8; nt++) {                                  \
                uint2 bv = *(const uint2*)(Bw + (wn * 8 + nt) * 128 + kc * 64 + lane * 2); \
                _Pragma("unroll")                                             \
                for (int mt = 0; mt < 4; mt++)                                \
                    mma16(acc[mt][nt], (const uint32_t*)&av[mt], (const uint32_t*)&bv); \
            }                                                                 \
        }                                                                     \
    }

// ---------------------------------------------------------------------------
// Phase 1: logits = x @ w^T. Epilogue: z partials (from acc), logits, probs.
// ---------------------------------------------------------------------------
__global__ __launch_bounds__(128, 2) void gemm1_kernel(float* __restrict__ out)
{
    extern __shared__ uint32_t sm[];
    const uint32_t smb = (uint32_t)__cvta_generic_to_shared(sm);
    GEMM_DECLS
    const int m0 = blockIdx.x * BM;
    const int n0 = blockIdx.y * BN;
    GEMM_ISSUE(g_xt, g_wt, KC1H)

    issue(0); issue(1);
    const int NK = HDIM / 32;   // 64
    for (int kt = 0; kt < NK; kt++) {
        if (kt + 1 < NK) cpa_wait1(); else cpa_wait0();
        __syncthreads();
        if (kt + 2 < NK) issue(kt + 2);
        GEMM_COMPUTE(kt)
    }

    // ---- z partials straight from fragments ----
    {
        float* zp = g_zpart + ((size_t)(blockIdx.y * 2 + wn)) * BT + m0;
        #pragma unroll
        for (int mt = 0; mt < 4; mt++) {
            float s0 = 0.f, s1 = 0.f;
            #pragma unroll
            for (int nt = 0; nt < 8; nt++) {
                s0 += __expf(acc[mt][nt][0]) + __expf(acc[mt][nt][1]);
                s1 += __expf(acc[mt][nt][2]) + __expf(acc[mt][nt][3]);
            }
            s0 += __shfl_xor_sync(0xFFFFFFFFu, s0, 1);
            s0 += __shfl_xor_sync(0xFFFFFFFFu, s0, 2);
            s1 += __shfl_xor_sync(0xFFFFFFFFu, s1, 1);
            s1 += __shfl_xor_sync(0xFFFFFFFFu, s1, 2);
            if (tg == 0) {
                zp[wm * 64 + mt * 16 + g]     = s0;
                zp[wm * 64 + mt * 16 + 8 + g] = s1;
            }
        }
    }

    // ---- stage full 128x128 tile, then logits + probs ----
    __syncthreads();
    float* sf = (float*)sm;                        // [128][132] = 67584 B
    #pragma unroll
    for (int mt = 0; mt < 4; mt++) {
        #pragma unroll
        for (int nt = 0; nt < 8; nt++) {
            int r = wm * 64 + mt * 16 + g;
            int c = wn * 64 + nt * 8 + tg * 2;
            sf[r * 132 + c]           = acc[mt][nt][0];
            sf[r * 132 + c + 1]       = acc[mt][nt][1];
            sf[(r + 8) * 132 + c]     = acc[mt][nt][2];
            sf[(r + 8) * 132 + c + 1] = acc[mt][nt][3];
        }
    }
    __syncthreads();

    float* outL = out + OUT_LOGITS;
    for (int i = 0; i < 128; i++)
        outL[(size_t)(m0 + i) * VDIM + n0 + tid] = sf[i * 132 + tid];

    // probs in fp16 A-perm layout: 8 m16 * 8 k16 = 64 units, 16 per warp
    #pragma unroll 4
    for (int u = 0; u < 16; u++) {
        int unit = wid * 16 + u;
        int t16 = unit >> 3, kc = unit & 7;
        int rb = t16 * 16;
        const float* s0 = sf + (rb + g) * 132 + kc * 16;
        const float* s1 = sf + (rb + 8 + g) * 132 + kc * 16;
        uint4 o;
        o.x = packh2(__expf(s0[2 * tg]),     __expf(s0[2 * tg + 1]));
        o.y = packh2(__expf(s1[2 * tg]),     __expf(s1[2 * tg + 1]));
        o.z = packh2(__expf(s0[2 * tg + 8]), __expf(s0[2 * tg + 9]));
        o.w = packh2(__expf(s1[2 * tg + 8]), __expf(s1[2 * tg + 9]));
        *(uint4*)(g_probs + ((size_t)(m0 / 16 + t16) * KC2H + n0 / 16 + kc) * 128
                  + lane * 4) = o;
    }
}

// ---------------------------------------------------------------------------
// Phase 2: zred — Z, lse, 1/Z, ntl. Target dtype runtime-detected
// (JAX x64-off downcasts int64 -> int32; odd words all-zero => int64).
// ---------------------------------------------------------------------------
__global__ void zred_kernel(const void* __restrict__ target,
                            float* __restrict__ out)
{
    __shared__ int oddor;
    const int tid = threadIdx.x;
    const int lane = tid & 31;
    const int wid = tid >> 5;
    const int row = blockIdx.x * 8 + wid;

    if (tid == 0) oddor = 0;
    __syncthreads();
    {
        const int* t32 = (const int*)target;
        int f = 0;
        for (int i = tid; i < BT / 2; i += 256) f |= t32[2 * i + 1];
        if (f) atomicOr(&oddor, 1);
    }
    __syncthreads();

    float s = 0.f;
    for (int t = lane; t < NZSL; t += 32)
        s += g_zpart[(size_t)t * BT + row];
    #pragma unroll
    for (int o = 16; o > 0; o >>= 1)
        s += __shfl_xor_sync(0xFFFFFFFFu, s, o);

    if (lane == 0) {
        out[OUT_LSE + row] = logf(s);
        g_scale[row] = 1.0f / s;
        long long t;
        if (oddor) t = (long long)((const int*)target)[row];
        else       t = ((const long long*)target)[row];
        if (t < 0) t = 0;
        if (t >= VDIM) t = VDIM - 1;
        out[OUT_NTL + row] = -out[OUT_LOGITS + (size_t)row * VDIM + t];
    }
}

__global__ void loss_kernel(float* __restrict__ out)
{
    __shared__ float red[256];
    const int tid = threadIdx.x;
    float s = 0.f;
    for (int i = tid; i < BT; i += 256)
        s += out[OUT_LSE + i] + out[OUT_NTL + i];
    red[tid] = s;
    __syncthreads();
    for (int st = 128; st > 0; st >>= 1) {
        if (tid < st) red[tid] += red[tid + st];
        __syncthreads();
    }
    if (tid == 0) out[OUT_LOSS] = red[0] / (float)BT;
}

// ---------------------------------------------------------------------------
// Phase 3: grad partials = E @ w (K-split x4), direct fragment stores
// ---------------------------------------------------------------------------
__global__ __launch_bounds__(128, 2) void gemm2_kernel()
{
    extern __shared__ uint32_t sm[];
    const uint32_t smb = (uint32_t)__cvta_generic_to_shared(sm);
    GEMM_DECLS
    const int m0 = blockIdx.x * BM;
    const int n0 = blockIdx.y * BN;
    const int s  = blockIdx.z;
    GEMM_ISSUE(g_probs, g_wt2, KC2H)

    const int kbase = s * (VDIM / 32 / SPLIT);    // 250 iters per split
    const int kend  = kbase + (VDIM / 32 / SPLIT);
    issue(kbase); issue(kbase + 1);
    for (int kt = kbase; kt < kend; kt++) {
        if (kt + 1 < kend) cpa_wait1(); else cpa_wait0();
        __syncthreads();
        if (kt + 2 < kend) issue(kt + 2);
        GEMM_COMPUTE(kt)
    }

    float* gp = g_gpart + (size_t)s * BT * HDIM;
    #pragma unroll
    for (int mt = 0; mt < 4; mt++) {
        #pragma unroll
        for (int nt = 0; nt < 8; nt++) {
            int r = m0 + wm * 64 + mt * 16 + g;
            int c = n0 + wn * 64 + nt * 8 + tg * 2;
            *(float2*)(gp + (size_t)r * HDIM + c) =
                make_float2(acc[mt][nt][0], acc[mt][nt][1]);
            *(float2*)(gp + (size_t)(r + 8) * HDIM + c) =
                make_float2(acc[mt][nt][2], acc[mt][nt][3]);
        }
    }
}

// ---------------------------------------------------------------------------
// Phase 4: grad_x = (sum_s partial) * 1/Z
// ---------------------------------------------------------------------------
__global__ void gradred_kernel(float* __restrict__ out)
{
    const int row = blockIdx.x;
    const float sc = g_scale[row];
    float* o = out + OUT_GRADX + (size_t)row * HDIM;
    const float* p = g_gpart + (size_t)row * HDIM;
    for (int c = threadIdx.x; c < HDIM; c += 256) {
        float v = p[c];
        #pragma unroll
        for (int s = 1; s < SPLIT; s++)
            v += p[(size_t)s * BT * HDIM + c];
        o[c] = v * sc;
    }
}

// ---------------------------------------------------------------------------
extern "C" void kernel_launch(void* const* d_in, const int* in_sizes, int n_in,
                              void* d_out, int out_size)
{
    const float* x   = (const float*)d_in[0];
    const float* w   = (const float*)d_in[1];
    const void*  tgt = d_in[2];
    float*       out = (float*)d_out;

    cudaFuncSetAttribute(gemm1_kernel,
        cudaFuncAttributeMaxDynamicSharedMemorySize, G1_SMEM);
    cudaFuncSetAttribute(gemm2_kernel,
        cudaFuncAttributeMaxDynamicSharedMemorySize, G2_SMEM);

    convA_kernel <<<512,  128>>>(x);
    convB1_kernel<<<4096, 128>>>(w);
    convB2_kernel<<<4096, 128>>>(w);

    dim3 g1(BT / BM, VDIM / BN);        // (32, 250), m-fastest
    gemm1_kernel<<<g1, 128, G1_SMEM>>>(out);

    zred_kernel<<<BT / 8, 256>>>(tgt, out);
    loss_kernel<<<1, 256>>>(out);

    dim3 g2(BT / BM, HDIM / BN, SPLIT); // (32, 16, 4) = 2048 CTAs
    gemm2_kernel<<<g2, 128, G2_SMEM>>>();
    gradred_kernel<<<BT, 256>>>(out);
}

// round 11
// speedup vs baseline: 2.3414x; 1.0773x over previous
#include <cuda_runtime.h>
#include <cuda_fp16.h>
#include <cstdint>

#define BT   4096
#define HDIM 2048
#define VDIM 32000
#define KC1H (HDIM / 16)           // 128 k16-chunks (gemm1)
#define KC2H (VDIM / 16)           // 2000 k16-chunks (gemm2)
#define SPLIT 4
#define NZSL 500                   // 250 n-tiles * 2 wn

// Output layout: [loss(1) | logits(BT*V) | lse(BT) | ntl(BT) | grad_x(BT*H)]
#define OUT_LOSS   0
#define OUT_LOGITS 1LL
#define OUT_LSE    (1LL + (long long)BT * VDIM)
#define OUT_NTL    (OUT_LSE + BT)
#define OUT_GRADX  (OUT_NTL + BT)

// Geometry: CTA 128x128, BK=32 (2 k16), 128 thr, 4 warps (2m x 2n), warp 64x64
#define BM 128
#define BN 128
#define STG_AW 2048                // 8 m16 * 2 kc * 128 words
#define STG_W  4096                // + 16 n8 * 2 kc * 64 words
#define G1_SMEM 67584              // max(4 stages = 65536, sf 128*132*4 = 67584)
#define G2_SMEM 65536              // 4 stages

// ---- scratch (fp16 fragment-major) ----
// A unit [m16][k16]: lane-> uint4 {(g,2tg|+1),(g+8,..),(g,2tg+8|+9),(g+8,..)}
// B unit [n8][k16]:  lane-> uint2 {(k=2tg|+1,n=g),(k=2tg+8|+9,n=g)}
__device__ uint32_t g_xt   [(size_t)(BT / 16) * KC1H * 128];
__device__ uint32_t g_wt   [(size_t)(VDIM / 8) * KC1H * 64];   // (n=v,k=h)
__device__ uint32_t g_wt2  [(size_t)(HDIM / 8) * KC2H * 64];   // (n=h,k=v)
__device__ uint32_t g_probs[(size_t)(BT / 16) * KC2H * 128];
__device__ float    g_gpart[(size_t)SPLIT * BT * HDIM];
__device__ float    g_zpart[(size_t)NZSL * BT];
__device__ float    g_scale[BT];

__device__ __forceinline__ uint32_t packh2(float lo, float hi) {
    __half2 h = __floats2half2_rn(lo, hi);
    return *(uint32_t*)&h;
}
__device__ __forceinline__ void mma16(float* d, const uint32_t* a, const uint32_t* b) {
    asm volatile(
        "mma.sync.aligned.m16n8k16.row.col.f32.f16.f16.f32 "
        "{%0,%1,%2,%3}, {%4,%5,%6,%7}, {%8,%9}, {%0,%1,%2,%3};\n"
        : "+f"(d[0]), "+f"(d[1]), "+f"(d[2]), "+f"(d[3])
        : "r"(a[0]), "r"(a[1]), "r"(a[2]), "r"(a[3]),
          "r"(b[0]), "r"(b[1]));
}
__device__ __forceinline__ void cpa16(uint32_t smem, const void* gmem) {
    asm volatile("cp.async.cg.shared.global [%0], [%1], 16;\n" :: "r"(smem), "l"(gmem));
}
__device__ __forceinline__ void cpa_commit() {
    asm volatile("cp.async.commit_group;\n" ::: "memory");
}
__device__ __forceinline__ void cpa_wait0() {
    asm volatile("cp.async.wait_group 0;\n" ::: "memory");
}
__device__ __forceinline__ void cpa_wait1() {
    asm volatile("cp.async.wait_group 1;\n" ::: "memory");
}
__device__ __forceinline__ void cpa_wait2() {
    asm volatile("cp.async.wait_group 2;\n" ::: "memory");
}

// ---------------------------------------------------------------------------
// Converters into fp16 fragment-major layouts
// ---------------------------------------------------------------------------
__global__ void convA_kernel(const float* __restrict__ x)
{
    const int lane = threadIdx.x & 31;
    const int g = lane >> 2, tg = lane & 3;
    const int warp = (blockIdx.x * blockDim.x + threadIdx.x) >> 5;
    const int nwarp = (gridDim.x * blockDim.x) >> 5;
    const int NF = (BT / 16) * KC1H;                 // 32768
    for (int f = warp; f < NF; f += nwarp) {
        int m16 = f >> 7, kc = f & (KC1H - 1);
        const float* p = x + (size_t)(m16 * 16 + g) * HDIM + kc * 16;
        uint4 o;
        o.x = packh2(p[2 * tg],            p[2 * tg + 1]);
        o.y = packh2(p[8 * HDIM + 2 * tg], p[8 * HDIM + 2 * tg + 1]);
        o.z = packh2(p[2 * tg + 8],        p[2 * tg + 9]);
        o.w = packh2(p[8 * HDIM + 2 * tg + 8], p[8 * HDIM + 2 * tg + 9]);
        *(uint4*)(g_xt + (size_t)f * 128 + lane * 4) = o;
    }
}
__global__ void convB1_kernel(const float* __restrict__ w)
{
    const int lane = threadIdx.x & 31;
    const int g = lane >> 2, tg = lane & 3;
    const int warp = (blockIdx.x * blockDim.x + threadIdx.x) >> 5;
    const int nwarp = (gridDim.x * blockDim.x) >> 5;
    const int NF = (VDIM / 8) * KC1H;                // 512000
    for (int f = warp; f < NF; f += nwarp) {
        int v8 = f >> 7, kc = f & (KC1H - 1);
        const float* p = w + (size_t)(v8 * 8 + g) * HDIM + kc * 16;
        uint2 o;
        o.x = packh2(p[2 * tg],     p[2 * tg + 1]);
        o.y = packh2(p[2 * tg + 8], p[2 * tg + 9]);
        *(uint2*)(g_wt + (size_t)f * 64 + lane * 2) = o;
    }
}
// Coalesced: 64x64 tile of w staged in smem (pad 68 -> conflict-free reads).
__global__ void convB2_kernel(const float* __restrict__ w)
{
    __shared__ float t[64][68];
    const int v0 = blockIdx.x * 64;      // 500
    const int h0 = blockIdx.y * 64;      // 32
    const int tid = threadIdx.x;         // 256
    #pragma unroll
    for (int i = 0; i < 4; i++) {
        int q = tid + i * 256;           // 1024 float4 chunks
        int r = q >> 4, c4 = q & 15;
        float4 v = *(const float4*)(w + (size_t)(v0 + r) * HDIM + h0 + c4 * 4);
        t[r][c4 * 4 + 0] = v.x; t[r][c4 * 4 + 1] = v.y;
        t[r][c4 * 4 + 2] = v.z; t[r][c4 * 4 + 3] = v.w;
    }
    __syncthreads();
    const int lane = tid & 31, wid = tid >> 5;
    const int g = lane >> 2, tg = lane & 3;
    const int h8 = h0 / 8 + wid;
    #pragma unroll
    for (int kc = 0; kc < 4; kc++) {
        int vb = kc * 16;
        uint2 o;
        o.x = packh2(t[vb + 2 * tg][wid * 8 + g],     t[vb + 2 * tg + 1][wid * 8 + g]);
        o.y = packh2(t[vb + 2 * tg + 8][wid * 8 + g], t[vb + 2 * tg + 9][wid * 8 + g]);
        *(uint2*)(g_wt2 + ((size_t)h8 * KC2H + v0 / 16 + kc) * 64 + lane * 2) = o;
    }
}

// ---------------------------------------------------------------------------
// mainloop pieces: 128x128 CTA, warp 64x64, BK=32 (2 k16), 4-stage, dist-3
// ---------------------------------------------------------------------------
#define GEMM_DECLS                                            \
    const int tid  = threadIdx.x;                             \
    const int lane = tid & 31;                                \
    const int wid  = tid >> 5;                                \
    const int g    = lane >> 2;                               \
    const int tg   = lane & 3;                                \
    const int wm   = wid & 1;                                 \
    const int wn   = wid >> 1;                                \
    float acc[4][8][4];                                       \
    _Pragma("unroll")                                         \
    for (int i = 0; i < 4; i++)                               \
        _Pragma("unroll")                                     \
        for (int j = 0; j < 8; j++)                           \
            _Pragma("unroll")                                 \
            for (int q = 0; q < 4; q++) acc[i][j][q] = 0.f;

#define GEMM_ISSUE(AG, BG, KCD)                                               \
    auto issue = [&](int kt) {                                                \
        const uint32_t sb = smb + (uint32_t)(kt & 3) * (STG_W * 4);           \
        const int kc0 = kt * 2;                                              \
        _Pragma("unroll")                                                     \
        for (int i = 0; i < 4; i++) {             /* A: 512 chunks */         \
            int q = tid + i * 128;                                            \
            int ai = q >> 6, rem = q & 63;                                    \
            int kcl = rem >> 5, c = rem & 31;                                 \
            cpa16(sb + (ai * 256 + kcl * 128 + c * 4) * 4,                    \
                  AG + ((size_t)(m0 / 16 + ai) * KCD + kc0 + kcl) * 128 + c * 4); \
        }                                                                     \
        _Pragma("unroll")                                                     \
        for (int i = 0; i < 4; i++) {             /* B: 512 chunks */         \
            int q = tid + i * 128;                                            \
            int bj = q >> 5, rem = q & 31;                                    \
            int kcl = rem >> 4, c = rem & 15;                                 \
            cpa16(sb + (STG_AW + bj * 128 + kcl * 64 + c * 4) * 4,            \
                  BG + ((size_t)(n0 / 8 + bj) * KCD + kc0 + kcl) * 64 + c * 4); \
        }                                                                     \
        cpa_commit();                                                         \
    };

#define GEMM_COMPUTE(kt)                                                      \
    {                                                                         \
        const uint32_t* Aw = sm + (kt & 3) * STG_W;                           \
        const uint32_t* Bw = Aw + STG_AW;                                     \
        _Pragma("unroll")                                                     \
        for (int kc = 0; kc < 2; kc++) {                                      \
            uint4 av[4];                                                      \
            _Pragma("unroll")                                                 \
            for (int mt = 0; mt < 4; mt++)                                    \
                av[mt] = *(const uint4*)(Aw + (wm * 4 + mt) * 256 + kc * 128 + lane * 4); \
            _Pragma("unroll")                                                 \
            for (int nt = 0; nt < 8; nt++) {                                  \
                uint2 bv = *(const uint2*)(Bw + (wn * 8 + nt) * 128 + kc * 64 + lane * 2); \
                _Pragma("unroll")                                             \
                for (int mt = 0; mt < 4; mt++)                                \
                    mma16(acc[mt][nt], (const uint32_t*)&av[mt], (const uint32_t*)&bv); \
            }                                                                 \
        }                                                                     \
    }

// pending groups at top of iter kt: {kt .. min(kt+2, kend-1)}
#define GEMM_WAIT(kt, kend)                                   \
    if ((kend) - (kt) >= 3)      cpa_wait2();                 \
    else if ((kend) - (kt) == 2) cpa_wait1();                 \
    else                         cpa_wait0();

// ---------------------------------------------------------------------------
// Phase 1: logits = x @ w^T. Epilogue: z partials (from acc), logits, probs.
// ---------------------------------------------------------------------------
__global__ __launch_bounds__(128, 2) void gemm1_kernel(float* __restrict__ out)
{
    extern __shared__ uint32_t sm[];
    const uint32_t smb = (uint32_t)__cvta_generic_to_shared(sm);
    GEMM_DECLS
    const int m0 = blockIdx.x * BM;
    const int n0 = blockIdx.y * BN;
    GEMM_ISSUE(g_xt, g_wt, KC1H)

    issue(0); issue(1); issue(2);
    const int NK = HDIM / 32;   // 64
    for (int kt = 0; kt < NK; kt++) {
        GEMM_WAIT(kt, NK)
        __syncthreads();
        if (kt + 3 < NK) issue(kt + 3);
        GEMM_COMPUTE(kt)
    }

    // ---- z partials straight from fragments ----
    {
        float* zp = g_zpart + ((size_t)(blockIdx.y * 2 + wn)) * BT + m0;
        #pragma unroll
        for (int mt = 0; mt < 4; mt++) {
            float s0 = 0.f, s1 = 0.f;
            #pragma unroll
            for (int nt = 0; nt < 8; nt++) {
                s0 += __expf(acc[mt][nt][0]) + __expf(acc[mt][nt][1]);
                s1 += __expf(acc[mt][nt][2]) + __expf(acc[mt][nt][3]);
            }
            s0 += __shfl_xor_sync(0xFFFFFFFFu, s0, 1);
            s0 += __shfl_xor_sync(0xFFFFFFFFu, s0, 2);
            s1 += __shfl_xor_sync(0xFFFFFFFFu, s1, 1);
            s1 += __shfl_xor_sync(0xFFFFFFFFu, s1, 2);
            if (tg == 0) {
                zp[wm * 64 + mt * 16 + g]     = s0;
                zp[wm * 64 + mt * 16 + 8 + g] = s1;
            }
        }
    }

    // ---- stage full 128x128 tile, then logits + probs ----
    __syncthreads();
    float* sf = (float*)sm;                        // [128][132] = 67584 B
    #pragma unroll
    for (int mt = 0; mt < 4; mt++) {
        #pragma unroll
        for (int nt = 0; nt < 8; nt++) {
            int r = wm * 64 + mt * 16 + g;
            int c = wn * 64 + nt * 8 + tg * 2;
            sf[r * 132 + c]           = acc[mt][nt][0];
            sf[r * 132 + c + 1]       = acc[mt][nt][1];
            sf[(r + 8) * 132 + c]     = acc[mt][nt][2];
            sf[(r + 8) * 132 + c + 1] = acc[mt][nt][3];
        }
    }
    __syncthreads();

    float* outL = out + OUT_LOGITS;
    for (int i = 0; i < 128; i++)
        outL[(size_t)(m0 + i) * VDIM + n0 + tid] = sf[i * 132 + tid];

    // probs in fp16 A-perm layout: 8 m16 * 8 k16 = 64 units, 16 per warp
    #pragma unroll 4
    for (int u = 0; u < 16; u++) {
        int unit = wid * 16 + u;
        int t16 = unit >> 3, kc = unit & 7;
        int rb = t16 * 16;
        const float* s0 = sf + (rb + g) * 132 + kc * 16;
        const float* s1 = sf + (rb + 8 + g) * 132 + kc * 16;
        uint4 o;
        o.x = packh2(__expf(s0[2 * tg]),     __expf(s0[2 * tg + 1]));
        o.y = packh2(__expf(s1[2 * tg]),     __expf(s1[2 * tg + 1]));
        o.z = packh2(__expf(s0[2 * tg + 8]), __expf(s0[2 * tg + 9]));
        o.w = packh2(__expf(s1[2 * tg + 8]), __expf(s1[2 * tg + 9]));
        *(uint4*)(g_probs + ((size_t)(m0 / 16 + t16) * KC2H + n0 / 16 + kc) * 128
                  + lane * 4) = o;
    }
}

// ---------------------------------------------------------------------------
// Phase 2: zred — Z, lse, 1/Z, ntl. Target dtype runtime-detected
// (JAX x64-off downcasts int64 -> int32; odd words all-zero => int64).
// ---------------------------------------------------------------------------
__global__ void zred_kernel(const void* __restrict__ target,
                            float* __restrict__ out)
{
    __shared__ int oddor;
    const int tid = threadIdx.x;
    const int lane = tid & 31;
    const int wid = tid >> 5;
    const int row = blockIdx.x * 8 + wid;

    if (tid == 0) oddor = 0;
    __syncthreads();
    {
        const int* t32 = (const int*)target;
        int f = 0;
        for (int i = tid; i < BT / 2; i += 256) f |= t32[2 * i + 1];
        if (f) atomicOr(&oddor, 1);
    }
    __syncthreads();

    float s = 0.f;
    for (int t = lane; t < NZSL; t += 32)
        s += g_zpart[(size_t)t * BT + row];
    #pragma unroll
    for (int o = 16; o > 0; o >>= 1)
        s += __shfl_xor_sync(0xFFFFFFFFu, s, o);

    if (lane == 0) {
        out[OUT_LSE + row] = logf(s);
        g_scale[row] = 1.0f / s;
        long long t;
        if (oddor) t = (long long)((const int*)target)[row];
        else       t = ((const long long*)target)[row];
        if (t < 0) t = 0;
        if (t >= VDIM) t = VDIM - 1;
        out[OUT_NTL + row] = -out[OUT_LOGITS + (size_t)row * VDIM + t];
    }
}

__global__ void loss_kernel(float* __restrict__ out)
{
    __shared__ float red[256];
    const int tid = threadIdx.x;
    float s = 0.f;
    for (int i = tid; i < BT; i += 256)
        s += out[OUT_LSE + i] + out[OUT_NTL + i];
    red[tid] = s;
    __syncthreads();
    for (int st = 128; st > 0; st >>= 1) {
        if (tid < st) red[tid] += red[tid + st];
        __syncthreads();
    }
    if (tid == 0) out[OUT_LOSS] = red[0] / (float)BT;
}

// ---------------------------------------------------------------------------
// Phase 3: grad partials = E @ w (K-split x4), direct fragment stores
// ---------------------------------------------------------------------------
__global__ __launch_bounds__(128, 2) void gemm2_kernel()
{
    extern __shared__ uint32_t sm[];
    const uint32_t smb = (uint32_t)__cvta_generic_to_shared(sm);
    GEMM_DECLS
    const int m0 = blockIdx.x * BM;
    const int n0 = blockIdx.y * BN;
    const int s  = blockIdx.z;
    GEMM_ISSUE(g_probs, g_wt2, KC2H)

    const int kbase = s * (VDIM / 32 / SPLIT);    // 250 iters per split
    const int kend  = kbase + (VDIM / 32 / SPLIT);
    issue(kbase); issue(kbase + 1); issue(kbase + 2);
    for (int kt = kbase; kt < kend; kt++) {
        GEMM_WAIT(kt, kend)
        __syncthreads();
        if (kt + 3 < kend) issue(kt + 3);
        GEMM_COMPUTE(kt)
    }

    float* gp = g_gpart + (size_t)s * BT * HDIM;
    #pragma unroll
    for (int mt = 0; mt < 4; mt++) {
        #pragma unroll
        for (int nt = 0; nt < 8; nt++) {
            int r = m0 + wm * 64 + mt * 16 + g;
            int c = n0 + wn * 64 + nt * 8 + tg * 2;
            *(float2*)(gp + (size_t)r * HDIM + c) =
                make_float2(acc[mt][nt][0], acc[mt][nt][1]);
            *(float2*)(gp + (size_t)(r + 8) * HDIM + c) =
                make_float2(acc[mt][nt][2], acc[mt][nt][3]);
        }
    }
}

// ---------------------------------------------------------------------------
// Phase 4: grad_x = (sum_s partial) * 1/Z
// ---------------------------------------------------------------------------
__global__ void gradred_kernel(float* __restrict__ out)
{
    const int row = blockIdx.x;
    const float sc = g_scale[row];
    float* o = out + OUT_GRADX + (size_t)row * HDIM;
    const float* p = g_gpart + (size_t)row * HDIM;
    for (int c = threadIdx.x; c < HDIM; c += 256) {
        float v = p[c];
        #pragma unroll
        for (int s = 1; s < SPLIT; s++)
            v += p[(size_t)s * BT * HDIM + c];
        o[c] = v * sc;
    }
}

// ---------------------------------------------------------------------------
extern "C" void kernel_launch(void* const* d_in, const int* in_sizes, int n_in,
                              void* d_out, int out_size)
{
    const float* x   = (const float*)d_in[0];
    const float* w   = (const float*)d_in[1];
    const void*  tgt = d_in[2];
    float*       out = (float*)d_out;

    cudaFuncSetAttribute(gemm1_kernel,
        cudaFuncAttributeMaxDynamicSharedMemorySize, G1_SMEM);
    cudaFuncSetAttribute(gemm2_kernel,
        cudaFuncAttributeMaxDynamicSharedMemorySize, G2_SMEM);

    convA_kernel <<<512,  128>>>(x);
    convB1_kernel<<<4096, 128>>>(w);
    convB2_kernel<<<dim3(VDIM / 64, HDIM / 64), 256>>>(w);

    dim3 g1(BT / BM, VDIM / BN);        // (32, 250), m-fastest
    gemm1_kernel<<<g1, 128, G1_SMEM>>>(out);

    zred_kernel<<<BT / 8, 256>>>(tgt, out);
    loss_kernel<<<1, 256>>>(out);

    dim3 g2(BT / BM, HDIM / BN, SPLIT); // (32, 16, 4) = 2048 CTAs
    gemm2_kernel<<<g2, 128, G2_SMEM>>>();
    gradred_kernel<<<BT, 256>>>(out);
}